// round 2
// baseline (speedup 1.0000x reference)
#include <cuda_runtime.h>

#define IMG_H 512
#define IMG_W 512
#define TW 32
#define TH 32
#define HALO 5
#define IW (TW + 2 * HALO)   // 42
#define IH (TH + 2 * HALO)   // 42
#define SROW 44              // padded row stride (floats) for sA/sB
#define HROW 34              // padded row stride (floats) for hh planes
#define NPIX (16LL * 3 * 512 * 512)
#define GRID_X (IMG_W / TW)
#define GRID_Y (IMG_H / TH)
#define GRID_Z 48
#define GRID_TOTAL (GRID_X * GRID_Y * GRID_Z)

typedef unsigned long long u64;

__device__ double g_sum;
__device__ unsigned int g_count;

__device__ __forceinline__ u64 pack2(float lo, float hi) {
    u64 r;
    asm("mov.b64 %0, {%1, %2};" : "=l"(r) : "f"(lo), "f"(hi));
    return r;
}
__device__ __forceinline__ void unpack2(u64 v, float& lo, float& hi) {
    asm("mov.b64 {%0, %1}, %2;" : "=f"(lo), "=f"(hi) : "l"(v));
}
__device__ __forceinline__ u64 fma2(u64 a, u64 b, u64 c) {
    u64 d;
    asm("fma.rn.f32x2 %0, %1, %2, %3;" : "=l"(d) : "l"(a), "l"(b), "l"(c));
    return d;
}
__device__ __forceinline__ u64 mul2(u64 a, u64 b) {
    u64 d;
    asm("mul.rn.f32x2 %0, %1, %2;" : "=l"(d) : "l"(a), "l"(b));
    return d;
}
__device__ __forceinline__ u64 add2(u64 a, u64 b) {
    u64 d;
    asm("add.rn.f32x2 %0, %1, %2;" : "=l"(d) : "l"(a), "l"(b));
    return d;
}
__device__ __forceinline__ u64 sub2(u64 a, u64 b) {
    u64 d;
    asm("sub.rn.f32x2 %0, %1, %2;" : "=l"(d) : "l"(a), "l"(b));
    return d;
}

__global__ __launch_bounds__(256, 2) void ssim_kernel(
    const float* __restrict__ A, const float* __restrict__ B,
    float* __restrict__ out)
{
    __shared__ float sA[IH][SROW];
    __shared__ float sB[IH][SROW];
    __shared__ float hh[5][IH][HROW];
    __shared__ float warp_sums[8];

    const int tid = threadIdx.x;
    const int plane = blockIdx.z;
    const int tx0 = blockIdx.x * TW;
    const int ty0 = blockIdx.y * TH;
    const float* a = A + (size_t)plane * IMG_H * IMG_W;
    const float* b = B + (size_t)plane * IMG_H * IMG_W;

    // Gaussian 1D window (sigma=1.5, K=11), normalized; packed duplicates.
    u64 w2[11];
    {
        float w[11], s = 0.f;
#pragma unroll
        for (int i = 0; i < 11; i++) {
            float d = (float)(i - 5);
            w[i] = expf(-d * d / 4.5f);
            s += w[i];
        }
        float inv = 1.f / s;
#pragma unroll
        for (int i = 0; i < 11; i++) w2[i] = pack2(w[i] * inv, w[i] * inv);
    }

    // ---- Load haloed 42x42 tile (zero pad outside image) ----
    for (int idx = tid; idx < IH * IW; idx += 256) {
        int r = idx / IW, c = idx % IW;
        int gy = ty0 - HALO + r;
        int gx = tx0 - HALO + c;
        float va = 0.f, vb = 0.f;
        if (gy >= 0 && gy < IMG_H && gx >= 0 && gx < IMG_W) {
            size_t o = (size_t)gy * IMG_W + gx;
            va = __ldg(a + o);
            vb = __ldg(b + o);
        }
        sA[r][c] = va;
        sB[r][c] = vb;
    }
    __syncthreads();

    // ---- Horizontal pass: 42 rows x 8 groups of 4 outputs (f32x2 packed) ----
    for (int g = tid; g < IH * 8; g += 256) {
        int r = g >> 3;
        int c0 = (g & 7) * 4;

        float va[14], vb[14];
#pragma unroll
        for (int j = 0; j < 7; j++) {
            float2 ta = *(const float2*)&sA[r][c0 + 2 * j];
            float2 tb = *(const float2*)&sB[r][c0 + 2 * j];
            va[2 * j] = ta.x; va[2 * j + 1] = ta.y;
            vb[2 * j] = tb.x; vb[2 * j + 1] = tb.y;
        }
        u64 pva[13], pvb[13];
#pragma unroll
        for (int j = 0; j < 13; j++) {
            pva[j] = pack2(va[j], va[j + 1]);
            pvb[j] = pack2(vb[j], vb[j + 1]);
        }

        u64 s0[2], s1[2], s2[2], s3[2], s4[2];
#pragma unroll
        for (int p = 0; p < 2; p++) {
            s0[p] = s1[p] = s2[p] = s3[p] = s4[p] = pack2(0.f, 0.f);
        }
#pragma unroll
        for (int k = 0; k < 11; k++) {
#pragma unroll
            for (int p = 0; p < 2; p++) {
                u64 xa = pva[k + 2 * p];
                u64 xb = pvb[k + 2 * p];
                u64 pa = mul2(w2[k], xa);
                u64 pb = mul2(w2[k], xb);
                s0[p] = add2(s0[p], pa);
                s1[p] = add2(s1[p], pb);
                s2[p] = fma2(pa, xa, s2[p]);
                s3[p] = fma2(pb, xb, s3[p]);
                s4[p] = fma2(pa, xb, s4[p]);
            }
        }
#pragma unroll
        for (int p = 0; p < 2; p++) {
            int c = c0 + 2 * p;
            float x, y;
            unpack2(s0[p], x, y); *(float2*)&hh[0][r][c] = make_float2(x, y);
            unpack2(s1[p], x, y); *(float2*)&hh[1][r][c] = make_float2(x, y);
            unpack2(s2[p], x, y); *(float2*)&hh[2][r][c] = make_float2(x, y);
            unpack2(s3[p], x, y); *(float2*)&hh[3][r][c] = make_float2(x, y);
            unpack2(s4[p], x, y); *(float2*)&hh[4][r][c] = make_float2(x, y);
        }
    }
    __syncthreads();

    // ---- Vertical pass: 128 threads, each owns 2 cols x 4 consecutive rows ----
    const float C1 = 0.0001f;
    const float C2 = 0.0009f;
    float accf = 0.f;
    if (tid < 128) {
        int xp = tid & 15;        // x pair 0..15
        int rg = tid >> 4;        // row group 0..7
        int r0 = rg * 4;
        int c = xp * 2;

        u64 m1[4], m2[4], e11[4], e22[4], e12[4];
#pragma unroll
        for (int i = 0; i < 4; i++) {
            m1[i] = m2[i] = e11[i] = e22[i] = e12[i] = pack2(0.f, 0.f);
        }
#pragma unroll
        for (int k = 0; k < 14; k++) {
            u64 h0 = *(const u64*)&hh[0][r0 + k][c];
            u64 h1 = *(const u64*)&hh[1][r0 + k][c];
            u64 h2 = *(const u64*)&hh[2][r0 + k][c];
            u64 h3 = *(const u64*)&hh[3][r0 + k][c];
            u64 h4 = *(const u64*)&hh[4][r0 + k][c];
#pragma unroll
            for (int i = 0; i < 4; i++) {
                int t = k - i;
                if (t >= 0 && t <= 10) {
                    m1[i]  = fma2(w2[t], h0, m1[i]);
                    m2[i]  = fma2(w2[t], h1, m2[i]);
                    e11[i] = fma2(w2[t], h2, e11[i]);
                    e22[i] = fma2(w2[t], h3, e22[i]);
                    e12[i] = fma2(w2[t], h4, e12[i]);
                }
            }
        }

        u64 two2 = pack2(2.f, 2.f);
        u64 c1p = pack2(C1, C1);
        u64 c2p = pack2(C2, C2);
#pragma unroll
        for (int i = 0; i < 4; i++) {
            u64 m1s = mul2(m1[i], m1[i]);
            u64 m2s = mul2(m2[i], m2[i]);
            u64 m12 = mul2(m1[i], m2[i]);
            u64 sig12 = sub2(e12[i], m12);
            u64 t1 = fma2(two2, m12, c1p);
            u64 t2 = fma2(two2, sig12, c2p);
            u64 num = mul2(t1, t2);
            u64 mss = add2(m1s, m2s);
            u64 v12 = sub2(add2(e11[i], e22[i]), mss);
            u64 d1 = add2(mss, c1p);
            u64 d2 = add2(v12, c2p);
            u64 den = mul2(d1, d2);
            float nx, ny, dx, dy;
            unpack2(num, nx, ny);
            unpack2(den, dx, dy);
            accf += __fdividef(nx, dx) + __fdividef(ny, dy);
        }
    }

    // ---- Block reduction ----
#pragma unroll
    for (int off = 16; off > 0; off >>= 1)
        accf += __shfl_down_sync(0xffffffffu, accf, off);
    if ((tid & 31) == 0) warp_sums[tid >> 5] = accf;
    __syncthreads();
    if (tid == 0) {
        float bsum = 0.f;
#pragma unroll
        for (int i = 0; i < 8; i++) bsum += warp_sums[i];
        atomicAdd(&g_sum, (double)bsum);
        __threadfence();
        unsigned int cold = atomicAdd(&g_count, 1u);
        if (cold == GRID_TOTAL - 1) {
            __threadfence();
            double s = *((volatile double*)&g_sum);
            out[0] = (float)(s / (double)NPIX);
            g_sum = 0.0;
            g_count = 0u;
            __threadfence();
        }
    }
}

extern "C" void kernel_launch(void* const* d_in, const int* in_sizes, int n_in,
                              void* d_out, int out_size)
{
    const float* A = (const float*)d_in[0];
    const float* B = (const float*)d_in[1];
    float* out = (float*)d_out;
    dim3 grid(GRID_X, GRID_Y, GRID_Z);
    ssim_kernel<<<grid, 256>>>(A, B, out);
}

// round 3
// speedup vs baseline: 1.3299x; 1.3299x over previous
#include <cuda_runtime.h>

#define IMG 512
#define TW 32
#define TH 32
#define IW 42
#define IH 42
#define HROW 34
#define PL (IH * HROW)            // 1428 floats per hh plane
#define NPIX (16LL * 3 * 512 * 512)
#define GRID_X 16
#define GRID_Y 16
#define GRID_Z 48
#define GRID_TOTAL (GRID_X * GRID_Y * GRID_Z)

typedef unsigned long long u64;

__device__ double g_sum;
__device__ unsigned int g_count;

// Gaussian(sigma=1.5, K=11) weights, normalized — compile-time constants.
#define WV0 0.00102850f
#define WV1 0.00759875f
#define WV2 0.03600077f
#define WV3 0.10936076f
#define WV4 0.21300550f
#define WV5 0.26601167f
__device__ __forceinline__ float wv(int t) {
    // t is always compile-time after unrolling -> immediate operand
    switch (t) {
        case 0: case 10: return WV0;
        case 1: case 9:  return WV1;
        case 2: case 8:  return WV2;
        case 3: case 7:  return WV3;
        case 4: case 6:  return WV4;
        default:         return WV5;
    }
}

__device__ __forceinline__ u64 pack2(float lo, float hi) {
    u64 r; asm("mov.b64 %0,{%1,%2};" : "=l"(r) : "f"(lo), "f"(hi)); return r;
}
__device__ __forceinline__ void unpack2(u64 v, float& lo, float& hi) {
    asm("mov.b64 {%0,%1},%2;" : "=f"(lo), "=f"(hi) : "l"(v));
}
__device__ __forceinline__ u64 fma2(u64 a, u64 b, u64 c) {
    u64 d; asm("fma.rn.f32x2 %0,%1,%2,%3;" : "=l"(d) : "l"(a), "l"(b), "l"(c)); return d;
}
__device__ __forceinline__ u64 mul2(u64 a, u64 b) {
    u64 d; asm("mul.rn.f32x2 %0,%1,%2;" : "=l"(d) : "l"(a), "l"(b)); return d;
}
__device__ __forceinline__ u64 add2(u64 a, u64 b) {
    u64 d; asm("add.rn.f32x2 %0,%1,%2;" : "=l"(d) : "l"(a), "l"(b)); return d;
}

__global__ __launch_bounds__(256, 4) void ssim_kernel(
    const float* __restrict__ A, const float* __restrict__ B,
    float* __restrict__ out)
{
    __shared__ float sA[IH][IW];
    __shared__ float sB[IH][IW];
    __shared__ float hh[5][IH][HROW];
    __shared__ float wsum[8];

    const int tid = threadIdx.x;
    const int plane = blockIdx.z;
    const int tx0 = blockIdx.x * TW;
    const int ty0 = blockIdx.y * TH;
    const float* a = A + (size_t)plane * IMG * IMG;
    const float* b = B + (size_t)plane * IMG * IMG;

    // ---- Stage haloed 42x42 tile, zero-padded (packed layout: addr == idx) ----
    float* sAf = &sA[0][0];
    float* sBf = &sB[0][0];
    for (int idx = tid; idx < IH * IW; idx += 256) {
        int r = idx / IW;
        int c = idx - r * IW;
        int gy = ty0 - 5 + r;
        int gx = tx0 - 5 + c;
        float va = 0.f, vb = 0.f;
        if (gy >= 0 && gy < IMG && gx >= 0 && gx < IMG) {
            size_t o = (size_t)gy * IMG + gx;
            va = __ldg(a + o);
            vb = __ldg(b + o);
        }
        sAf[idx] = va;
        sBf[idx] = vb;
    }
    __syncthreads();

    // Packed (duplicated) weights for the f32x2 horizontal pass.
    const u64 W0p = pack2(WV0, WV0), W1p = pack2(WV1, WV1), W2p = pack2(WV2, WV2);
    const u64 W3p = pack2(WV3, WV3), W4p = pack2(WV4, WV4), W5p = pack2(WV5, WV5);

    // Even/odd aligned-pair horizontal 11-tap conv: 4 outputs per call.
    auto hplane = [&](const u64* q, float* dst) {
        u64 E2a = fma2(W0p, add2(q[0], q[5]),
                  fma2(W2p, add2(q[1], q[4]),
                  mul2(W4p, add2(q[2], q[3]))));
        u64 E2b = fma2(W0p, add2(q[1], q[6]),
                  fma2(W2p, add2(q[2], q[5]),
                  mul2(W4p, add2(q[3], q[4]))));
        u64 Oa  = fma2(W1p, add2(q[0], q[4]),
                  fma2(W3p, add2(q[1], q[3]), mul2(W5p, q[2])));
        u64 Ob  = fma2(W1p, add2(q[1], q[5]),
                  fma2(W3p, add2(q[2], q[4]), mul2(W5p, q[3])));
        u64 Oc  = fma2(W1p, add2(q[2], q[6]),
                  fma2(W3p, add2(q[3], q[5]), mul2(W5p, q[4])));
        float oal, oah, obl, obh, ocl, och;
        unpack2(Oa, oal, oah);
        unpack2(Ob, obl, obh);
        unpack2(Oc, ocl, och);
        u64 o01 = add2(E2a, pack2(oah, obl));
        u64 o23 = add2(E2b, pack2(obh, ocl));
        *(u64*)(dst)     = o01;
        *(u64*)(dst + 2) = o23;
    };

    // ---- Horizontal pass: 42 rows x 8 groups of 4 outputs ----
    for (int g = tid; g < IH * 8; g += 256) {
        int r = g >> 3;
        int c0 = (g & 7) << 2;
        const float* rowA = &sA[r][c0];
        const float* rowB = &sB[r][c0];
        float* dst = &hh[0][r][c0];
        u64 q[7];
#pragma unroll
        for (int j = 0; j < 7; j++) q[j] = *(const u64*)(rowA + 2 * j);
        hplane(q, dst);                       // plane A
#pragma unroll
        for (int j = 0; j < 7; j++) q[j] = mul2(q[j], q[j]);
        hplane(q, dst + 2 * PL);              // plane A^2
#pragma unroll
        for (int j = 0; j < 7; j++) q[j] = *(const u64*)(rowB + 2 * j);
        hplane(q, dst + PL);                  // plane B
#pragma unroll
        for (int j = 0; j < 7; j++) q[j] = mul2(q[j], q[j]);
        hplane(q, dst + 3 * PL);              // plane B^2
#pragma unroll
        for (int j = 0; j < 7; j++)
            q[j] = mul2(*(const u64*)(rowA + 2 * j), *(const u64*)(rowB + 2 * j));
        hplane(q, dst + 4 * PL);              // plane AB
    }
    __syncthreads();

    // ---- Vertical pass: 128 threads, 1 col x 8 rows each; scalar FFMA-imm ----
    const float C1 = 0.0001f;
    const float C2 = 0.0009f;
    float accf = 0.f;
    if (tid < 128) {
        int c = tid & 31;
        int rg = tid >> 5;                    // 0..3
        const float* h0 = &hh[0][rg * 8][c];

        float acc[5][8];
#pragma unroll
        for (int p = 0; p < 5; p++)
#pragma unroll
            for (int i = 0; i < 8; i++) acc[p][i] = 0.f;

#pragma unroll
        for (int k = 0; k < 18; k++) {
            float v0 = h0[k * HROW];
            float v1 = h0[k * HROW + PL];
            float v2 = h0[k * HROW + 2 * PL];
            float v3 = h0[k * HROW + 3 * PL];
            float v4 = h0[k * HROW + 4 * PL];
#pragma unroll
            for (int i = 0; i < 8; i++) {
                int t = k - i;
                if (t >= 0 && t <= 10) {
                    float w = wv(t);
                    acc[0][i] += w * v0;
                    acc[1][i] += w * v1;
                    acc[2][i] += w * v2;
                    acc[3][i] += w * v3;
                    acc[4][i] += w * v4;
                }
            }
        }

#pragma unroll
        for (int i = 0; i < 8; i++) {
            float m1 = acc[0][i], m2 = acc[1][i];
            float e11 = acc[2][i], e22 = acc[3][i], e12 = acc[4][i];
            float m1s = m1 * m1;
            float m2s = m2 * m2;
            float m12 = m1 * m2;
            float mss = m1s + m2s;
            float p2 = m12 + m12;
            float t2 = e12 + e12;
            float n1 = p2 + C1;
            float n2 = (t2 - p2) + C2;
            float d1 = mss + C1;
            float d2 = ((e11 + e22) - mss) + C2;
            accf += __fdividef(n1 * n2, d1 * d2);
        }
    }

    // ---- Block reduction + single-pass finalize ----
#pragma unroll
    for (int off = 16; off > 0; off >>= 1)
        accf += __shfl_down_sync(0xffffffffu, accf, off);
    if ((tid & 31) == 0) wsum[tid >> 5] = accf;
    __syncthreads();
    if (tid == 0) {
        float bsum = 0.f;
#pragma unroll
        for (int i = 0; i < 8; i++) bsum += wsum[i];
        atomicAdd(&g_sum, (double)bsum);
        __threadfence();
        unsigned int cold = atomicAdd(&g_count, 1u);
        if (cold == GRID_TOTAL - 1) {
            __threadfence();
            double s = *((volatile double*)&g_sum);
            out[0] = (float)(s / (double)NPIX);
            g_sum = 0.0;
            g_count = 0u;
            __threadfence();
        }
    }
}

extern "C" void kernel_launch(void* const* d_in, const int* in_sizes, int n_in,
                              void* d_out, int out_size)
{
    const float* A = (const float*)d_in[0];
    const float* B = (const float*)d_in[1];
    float* out = (float*)d_out;
    dim3 grid(GRID_X, GRID_Y, GRID_Z);
    ssim_kernel<<<grid, 256>>>(A, B, out);
}

// round 4
// speedup vs baseline: 1.3494x; 1.0147x over previous
#include <cuda_runtime.h>

#define IMG 512
#define TW 32
#define TH 32
#define IW 42
#define IH 42
#define HROW 34
#define PL (IH * HROW)            // 1428 floats per hh plane
#define NPIX (16LL * 3 * 512 * 512)
#define GRID_X 16
#define GRID_Y 16
#define GRID_Z 48
#define GRID_TOTAL (GRID_X * GRID_Y * GRID_Z)

typedef unsigned long long u64;

__device__ double g_sum;
__device__ unsigned int g_count;

// Gaussian(sigma=1.5, K=11) weights, normalized — compile-time constants.
#define WV0 0.00102838f
#define WV1 0.00759876f
#define WV2 0.03600077f
#define WV3 0.10936069f
#define WV4 0.21300553f
#define WV5 0.26601172f

__device__ __forceinline__ u64 pack2(float lo, float hi) {
    u64 r; asm("mov.b64 %0,{%1,%2};" : "=l"(r) : "f"(lo), "f"(hi)); return r;
}
__device__ __forceinline__ void unpack2(u64 v, float& lo, float& hi) {
    asm("mov.b64 {%0,%1},%2;" : "=f"(lo), "=f"(hi) : "l"(v));
}
__device__ __forceinline__ u64 fma2(u64 a, u64 b, u64 c) {
    u64 d; asm("fma.rn.f32x2 %0,%1,%2,%3;" : "=l"(d) : "l"(a), "l"(b), "l"(c)); return d;
}
__device__ __forceinline__ u64 mul2(u64 a, u64 b) {
    u64 d; asm("mul.rn.f32x2 %0,%1,%2;" : "=l"(d) : "l"(a), "l"(b)); return d;
}
__device__ __forceinline__ u64 add2(u64 a, u64 b) {
    u64 d; asm("add.rn.f32x2 %0,%1,%2;" : "=l"(d) : "l"(a), "l"(b)); return d;
}
__device__ __forceinline__ u64 sub2(u64 a, u64 b) {
    u64 d; asm("sub.rn.f32x2 %0,%1,%2;" : "=l"(d) : "l"(a), "l"(b)); return d;
}

__global__ __launch_bounds__(256, 4) void ssim_kernel(
    const float* __restrict__ A, const float* __restrict__ B,
    float* __restrict__ out)
{
    __shared__ __align__(16) float sA[IH][IW];
    __shared__ __align__(16) float sB[IH][IW];
    __shared__ __align__(16) float hh[5][IH][HROW];
    __shared__ float wsum[8];

    const int tid = threadIdx.x;
    const int plane = blockIdx.z;
    const int tx0 = blockIdx.x * TW;
    const int ty0 = blockIdx.y * TH;
    const float* a = A + (size_t)plane * IMG * IMG;
    const float* b = B + (size_t)plane * IMG * IMG;

    // ---- Stage haloed 42x42 tile, zero-padded (packed layout: addr == idx) ----
    float* sAf = &sA[0][0];
    float* sBf = &sB[0][0];
    for (int idx = tid; idx < IH * IW; idx += 256) {
        int r = idx / IW;
        int c = idx - r * IW;
        int gy = ty0 - 5 + r;
        int gx = tx0 - 5 + c;
        float va = 0.f, vb = 0.f;
        if (gy >= 0 && gy < IMG && gx >= 0 && gx < IMG) {
            size_t o = (size_t)gy * IMG + gx;
            va = __ldg(a + o);
            vb = __ldg(b + o);
        }
        sAf[idx] = va;
        sBf[idx] = vb;
    }
    __syncthreads();

    // Packed (duplicated) weights.
    const u64 W0p = pack2(WV0, WV0), W1p = pack2(WV1, WV1), W2p = pack2(WV2, WV2);
    const u64 W3p = pack2(WV3, WV3), W4p = pack2(WV4, WV4), W5p = pack2(WV5, WV5);

    auto wp = [&](int t) -> u64 {
        switch (t) {
            case 0: case 10: return W0p;
            case 1: case 9:  return W1p;
            case 2: case 8:  return W2p;
            case 3: case 7:  return W3p;
            case 4: case 6:  return W4p;
            default:         return W5p;
        }
    };

    // Even/odd aligned-pair horizontal 11-tap conv: 4 outputs per call.
    auto hplane = [&](const u64* q, float* dst) {
        u64 E2a = fma2(W0p, add2(q[0], q[5]),
                  fma2(W2p, add2(q[1], q[4]),
                  mul2(W4p, add2(q[2], q[3]))));
        u64 E2b = fma2(W0p, add2(q[1], q[6]),
                  fma2(W2p, add2(q[2], q[5]),
                  mul2(W4p, add2(q[3], q[4]))));
        u64 Oa  = fma2(W1p, add2(q[0], q[4]),
                  fma2(W3p, add2(q[1], q[3]), mul2(W5p, q[2])));
        u64 Ob  = fma2(W1p, add2(q[1], q[5]),
                  fma2(W3p, add2(q[2], q[4]), mul2(W5p, q[3])));
        u64 Oc  = fma2(W1p, add2(q[2], q[6]),
                  fma2(W3p, add2(q[3], q[5]), mul2(W5p, q[4])));
        float oal, oah, obl, obh, ocl, och;
        unpack2(Oa, oal, oah);
        unpack2(Ob, obl, obh);
        unpack2(Oc, ocl, och);
        *(u64*)(dst)     = add2(E2a, pack2(oah, obl));
        *(u64*)(dst + 2) = add2(E2b, pack2(obh, ocl));
    };

    // ---- Horizontal pass: 42 rows x 8 groups of 4 outputs ----
    for (int g = tid; g < IH * 8; g += 256) {
        int r = g >> 3;
        int c0 = (g & 7) << 2;
        const float* rowA = &sA[r][c0];
        const float* rowB = &sB[r][c0];
        float* dst = &hh[0][r][c0];
        u64 qa[7], qb[7];
#pragma unroll
        for (int j = 0; j < 7; j++) qa[j] = *(const u64*)(rowA + 2 * j);
        hplane(qa, dst);                                  // A
#pragma unroll
        for (int j = 0; j < 7; j++) qa[j] = mul2(qa[j], qa[j]);
        hplane(qa, dst + 2 * PL);                         // A^2
#pragma unroll
        for (int j = 0; j < 7; j++) qb[j] = *(const u64*)(rowB + 2 * j);
        hplane(qb, dst + PL);                             // B
#pragma unroll
        for (int j = 0; j < 7; j++)
            qa[j] = mul2(*(const u64*)(rowA + 2 * j), qb[j]);
        hplane(qa, dst + 4 * PL);                         // AB
#pragma unroll
        for (int j = 0; j < 7; j++) qb[j] = mul2(qb[j], qb[j]);
        hplane(qb, dst + 3 * PL);                         // B^2
    }
    __syncthreads();

    // ---- Vertical pass: 128 threads, each 2 cols x 4 rows, f32x2 ----
    const float C1 = 0.0001f;
    const float C2 = 0.0009f;
    float accf = 0.f;
    if (tid < 128) {
        int xp = tid & 15;        // column pair 0..15
        int rg = tid >> 4;        // row group 0..7
        const float* hp = &hh[0][rg * 4][2 * xp];

        u64 zero = pack2(0.f, 0.f);
        // Sweep 1: planes 0 (m1), 1 (m2), 4 (e12)
        u64 a0[4], a1[4], a4[4];
#pragma unroll
        for (int i = 0; i < 4; i++) { a0[i] = a1[i] = a4[i] = zero; }
#pragma unroll
        for (int k = 0; k < 14; k++) {
            u64 L0 = *(const u64*)(hp + k * HROW);
            u64 L1 = *(const u64*)(hp + k * HROW + PL);
            u64 L4 = *(const u64*)(hp + k * HROW + 4 * PL);
#pragma unroll
            for (int i = 0; i < 4; i++) {
                int t = k - i;
                if (t >= 0 && t <= 10) {
                    u64 w = wp(t);
                    a0[i] = fma2(w, L0, a0[i]);
                    a1[i] = fma2(w, L1, a1[i]);
                    a4[i] = fma2(w, L4, a4[i]);
                }
            }
        }
        // Sweep 2: planes 2 (e11), 3 (e22)
        u64 a2[4], a3[4];
#pragma unroll
        for (int i = 0; i < 4; i++) { a2[i] = a3[i] = zero; }
#pragma unroll
        for (int k = 0; k < 14; k++) {
            u64 L2 = *(const u64*)(hp + k * HROW + 2 * PL);
            u64 L3 = *(const u64*)(hp + k * HROW + 3 * PL);
#pragma unroll
            for (int i = 0; i < 4; i++) {
                int t = k - i;
                if (t >= 0 && t <= 10) {
                    u64 w = wp(t);
                    a2[i] = fma2(w, L2, a2[i]);
                    a3[i] = fma2(w, L3, a3[i]);
                }
            }
        }

        const u64 c1p = pack2(C1, C1);
        const u64 c2p = pack2(C2, C2);
#pragma unroll
        for (int i = 0; i < 4; i++) {
            u64 m1 = a0[i], m2 = a1[i];
            u64 m1s = mul2(m1, m1);
            u64 m2s = mul2(m2, m2);
            u64 m12 = mul2(m1, m2);
            u64 mss = add2(m1s, m2s);
            u64 p2  = add2(m12, m12);
            u64 t2  = add2(a4[i], a4[i]);
            u64 n1  = add2(p2, c1p);
            u64 n2  = add2(sub2(t2, p2), c2p);
            u64 d1  = add2(mss, c1p);
            u64 d2  = add2(sub2(add2(a2[i], a3[i]), mss), c2p);
            u64 num = mul2(n1, n2);
            u64 den = mul2(d1, d2);
            float nx, ny, dx, dy;
            unpack2(num, nx, ny);
            unpack2(den, dx, dy);
            accf += __fdividef(nx, dx) + __fdividef(ny, dy);
        }
    }

    // ---- Block reduction + single-pass finalize ----
#pragma unroll
    for (int off = 16; off > 0; off >>= 1)
        accf += __shfl_down_sync(0xffffffffu, accf, off);
    if ((tid & 31) == 0) wsum[tid >> 5] = accf;
    __syncthreads();
    if (tid == 0) {
        float bsum = 0.f;
#pragma unroll
        for (int i = 0; i < 8; i++) bsum += wsum[i];
        atomicAdd(&g_sum, (double)bsum);
        __threadfence();
        unsigned int cold = atomicAdd(&g_count, 1u);
        if (cold == GRID_TOTAL - 1) {
            __threadfence();
            double s = *((volatile double*)&g_sum);
            out[0] = (float)(s / (double)NPIX);
            g_sum = 0.0;
            g_count = 0u;
            __threadfence();
        }
    }
}

extern "C" void kernel_launch(void* const* d_in, const int* in_sizes, int n_in,
                              void* d_out, int out_size)
{
    const float* A = (const float*)d_in[0];
    const float* B = (const float*)d_in[1];
    float* out = (float*)d_out;
    dim3 grid(GRID_X, GRID_Y, GRID_Z);
    ssim_kernel<<<grid, 256>>>(A, B, out);
}